// round 7
// baseline (speedup 1.0000x reference)
#include <cuda_runtime.h>
#include <math.h>

#define BB 32
#define CC 512
#define TT 1024
#define KS 13
#define RAD 6
#define TILE_C 32
#define TILE_T 32
#define NTILES (TT / TILE_T)          // 32
#define NTHR 96                        // 2 producer warps + 1 consumer warp
#define NPROD 64
#define ROWS (TILE_C + 2 * RAD)       // 44
#define SROW 36                        // padded row stride -> conflict-free LDS/STS.128
#define DROW 36
#define NBUF 6                         // cp.async ring depth (5 tiles in flight)
#define THRV 0.5f
#define BETA 0.95f

#define IN_TILE (ROWS * SROW)         // 1584 floats
#define DR_TILE (TILE_C * DROW)       // 1152 floats
#define SMEM_FLOATS (NBUF * IN_TILE + 2 * DR_TILE)   // 11808 floats = 47232 B

typedef unsigned long long ull;

__device__ __forceinline__ void cp_async_16(unsigned saddr, const void* gptr, int src_sz) {
    asm volatile("cp.async.ca.shared.global [%0], [%1], 16, %2;\n"
                 :: "r"(saddr), "l"(gptr), "r"(src_sz));
}
__device__ __forceinline__ void cp_commit() {
    asm volatile("cp.async.commit_group;\n");
}
__device__ __forceinline__ void cp_wait5() {
    asm volatile("cp.async.wait_group 5;\n");
}
__device__ __forceinline__ void bar_prod() {      // named barrier: 2 producer warps
    asm volatile("bar.sync 1, 64;\n" ::: "memory");
}
// packed f32x2 FMA: two independent correctly-rounded fp32 FMAs (bit-exact per lane)
__device__ __forceinline__ void ffma2(ull& d, ull a, ull b) {
    asm("fma.rn.f32x2 %0, %1, %2, %0;" : "+l"(d) : "l"(a), "l"(b));
}
__device__ __forceinline__ ull pack2(float a) {
    ull r;
    asm("mov.b64 %0, {%1, %2};" : "=l"(r) : "f"(a), "f"(a));
    return r;
}
union V2 { ulonglong2 u; float4 f; };

// Producers cooperatively load ROWS x TILE_T tile (channel halo, zero-filled OOB).
// 44*8 = 352 float4 transfers over 64 threads.
__device__ __forceinline__ void load_tile(const float* __restrict__ xb,
                                          int c0, int t0, float* __restrict__ sbuf,
                                          int ptid) {
#pragma unroll
    for (int it = 0; it < 6; ++it) {
        int i = ptid + it * NPROD;
        if (i < ROWS * (TILE_T / 4)) {
            int r = i >> 3;          // 0..43
            int g = i & 7;
            int ch = c0 + r - RAD;
            bool valid = ((unsigned)ch < (unsigned)CC);
            const float* gp = xb + (size_t)(valid ? ch : 0) * TT + t0 + g * 4;
            unsigned sa = (unsigned)__cvta_generic_to_shared(sbuf + r * SROW + g * 4);
            cp_async_16(sa, gp, valid ? 16 : 0);
        }
    }
}

extern __shared__ float smem[];

__global__ void __launch_bounds__(NTHR, 4)
snn_ws7(const float* __restrict__ x,
        const float* __restrict__ wp,
        float* __restrict__ out) {
    const int tid = threadIdx.x;
    const bool producer = (tid < NPROD);
    const int ptid = tid;
    const int ctid = tid - NPROD;         // consumer channel within tile (0..31)
    const int c0 = blockIdx.x * TILE_C;
    const int b  = blockIdx.y;

    const float* xb = x + (size_t)b * CC * TT;

    float* IN = smem;                     // NBUF tiles of ROWS x SROW
    float* DR = smem + NBUF * IN_TILE;    // 2 tiles of TILE_C x DROW

    // ---- producer setup: Gaussian taps (R1-exact values) ----
    ull kp[KS];
    int s = 0, g = 0;
    if (producer) {
        s = ptid >> 3;                    // channel strip (0..7): channels s*4..s*4+3
        g = ptid & 7;                     // float4 t-group (0..7)
        float wv = wp[0];
        float sigma = 0.5f * (1.0f + 10.0f) + fminf(fmaxf(wv, 1.0f), 10.0f);
        float inv2s2 = 0.5f / (sigma * sigma);
        float kw[KS];
        float ksum = 0.0f;
#pragma unroll
        for (int j = 0; j < KS; ++j) {
            float r = (float)(j - RAD);
            kw[j] = expf(-r * r * inv2s2);
            ksum += kw[j];
        }
        float kinv = 1.0f / ksum;
#pragma unroll
        for (int j = 0; j < KS; ++j) kp[j] = pack2(kw[j] * kinv);

        // prologue: tiles 0..4 in flight (depth-5 prefetch)
#pragma unroll
        for (int p = 0; p < NBUF - 1; ++p) {
            load_tile(xb, c0, p * TILE_T, IN + p * IN_TILE, ptid);
            cp_commit();
        }
    }

    float mem = 0.0f;                     // consumer LIF state
    float* outb = out + (size_t)b * CC * TT + (size_t)(c0 + ctid) * TT;

    for (int i = 0; i < NTILES; ++i) {
        if (producer) {
            if (i + NBUF - 1 < NTILES)
                load_tile(xb, c0, (i + NBUF - 1) * TILE_T,
                          IN + ((i + NBUF - 1) % NBUF) * IN_TILE, ptid);
            cp_commit();                  // commit every iter -> uniform group count
            cp_wait5();                   // 5 newest outstanding => tile i landed
            bar_prod();

            // ---- strip-4 conv of tile i: rows s*4 .. s*4+15, outputs ch s*4+k ----
            const float* sb = IN + (i % NBUF) * IN_TILE + (s * 4) * SROW + g * 4;
            V2 acc[4], xc[4];
#pragma unroll
            for (int k = 0; k < 4; ++k) { acc[k].u.x = 0ull; acc[k].u.y = 0ull; }
#pragma unroll
            for (int m = 0; m < 16; ++m) {
                V2 v;
                v.u = *(const ulonglong2*)(sb + m * SROW);
#pragma unroll
                for (int k = 0; k < 4; ++k) {
                    int j = m - k;
                    if (j >= 0 && j < KS) {
                        ffma2(acc[k].u.x, v.u.x, kp[j]);
                        ffma2(acc[k].u.y, v.u.y, kp[j]);
                        if (j == RAD) xc[k] = v;
                    }
                }
            }
            float* dst = DR + (i & 1) * DR_TILE + (s * 4) * DROW + g * 4;
#pragma unroll
            for (int k = 0; k < 4; ++k) {
                float4 d4;
                d4.x = xc[k].f.x - acc[k].f.x;
                d4.y = xc[k].f.y - acc[k].f.y;
                d4.z = xc[k].f.z - acc[k].f.z;
                d4.w = xc[k].f.w - acc[k].f.w;
                *(float4*)(dst + k * DROW) = d4;
            }
        }

        __syncthreads();    // publish DR[i&1]; consumers done with DR[i&1] of iter i-2

        if (!producer) {
            // ---- LIF scan tile i (bit-identical to R1) ----
            const float* dr = DR + (i & 1) * DR_TILE + ctid * DROW;
            float* ob = outb + (size_t)i * TILE_T;
#pragma unroll
            for (int gg = 0; gg < 8; ++gg) {
                float4 d4 = *(const float4*)(dr + gg * 4);
                float4 spk;
                mem = fmaf(BETA, mem, d4.x) - ((mem > THRV) ? THRV : 0.0f);
                spk.x = (mem > THRV) ? 1.0f : 0.0f;
                mem = fmaf(BETA, mem, d4.y) - ((mem > THRV) ? THRV : 0.0f);
                spk.y = (mem > THRV) ? 1.0f : 0.0f;
                mem = fmaf(BETA, mem, d4.z) - ((mem > THRV) ? THRV : 0.0f);
                spk.z = (mem > THRV) ? 1.0f : 0.0f;
                mem = fmaf(BETA, mem, d4.w) - ((mem > THRV) ? THRV : 0.0f);
                spk.w = (mem > THRV) ? 1.0f : 0.0f;
                *(float4*)(ob + gg * 4) = spk;
            }
        }
    }
}

extern "C" void kernel_launch(void* const* d_in, const int* in_sizes, int n_in,
                              void* d_out, int out_size) {
    const float* inp = (const float*)d_in[0];
    const float* wv  = (const float*)d_in[1];
    float* out       = (float*)d_out;

    cudaFuncSetAttribute(snn_ws7, cudaFuncAttributeMaxDynamicSharedMemorySize,
                         SMEM_FLOATS * 4);

    dim3 grid(CC / TILE_C, BB);   // (16, 32) = 512 CTAs
    dim3 blk(NTHR);               // 96 threads: 2 producer + 1 consumer warps
    snn_ws7<<<grid, blk, SMEM_FLOATS * 4>>>(inp, wv, out);
}

// round 8
// speedup vs baseline: 1.1288x; 1.1288x over previous
#include <cuda_runtime.h>
#include <math.h>

#define BB 32
#define CC 512
#define TT 1024
#define KS 13
#define RAD 6
#define TILE_C 32
#define TILE_T 64
#define NTILES (TT / TILE_T)          // 16
#define NTHR 96                        // 2 producer warps + 1 consumer warp
#define NPROD 64
#define ROWS (TILE_C + 2 * RAD)       // 44
#define SROW 68                        // 64 + 4 pad (floats)
#define DROW 68
#define NBUF 3
#define THRV 0.5f
#define BETA 0.95f

#define IN_TILE (ROWS * SROW)         // 2992 floats
#define DR_TILE (TILE_C * DROW)       // 2176 floats
#define SMEM_FLOATS (NBUF * IN_TILE + 2 * DR_TILE)   // 13328 floats = 53312 B

typedef unsigned long long ull;

__device__ __forceinline__ void cp_async_16(unsigned saddr, const void* gptr, int src_sz) {
    asm volatile("cp.async.ca.shared.global [%0], [%1], 16, %2;\n"
                 :: "r"(saddr), "l"(gptr), "r"(src_sz));
}
__device__ __forceinline__ void cp_commit() {
    asm volatile("cp.async.commit_group;\n");
}
__device__ __forceinline__ void cp_wait2() {
    asm volatile("cp.async.wait_group 2;\n");
}
__device__ __forceinline__ void bar_prod() {      // named barrier: 2 producer warps
    asm volatile("bar.sync 1, 64;\n" ::: "memory");
}
// packed f32x2 FMA: two independent correctly-rounded fp32 FMAs (bit-exact per lane)
__device__ __forceinline__ void ffma2(ull& d, ull a, ull b) {
    asm("fma.rn.f32x2 %0, %1, %2, %0;" : "+l"(d) : "l"(a), "l"(b));
}
__device__ __forceinline__ ull pack2(float a) {
    ull r;
    asm("mov.b64 %0, {%1, %2};" : "=l"(r) : "f"(a), "f"(a));
    return r;
}
union V2 { ulonglong2 u; float4 f; };

// Producers cooperatively load ROWS x TILE_T tile (channel halo, zero-filled OOB).
// 44 rows * 16 quads = 704 float4 over 64 threads = 11 iterations.
// Lanes map t-contiguous: each warp-op covers 2 rows x 256B (coalesced).
__device__ __forceinline__ void load_tile(const float* __restrict__ xb,
                                          int c0, int t0, float* __restrict__ sbuf,
                                          int ptid) {
#pragma unroll
    for (int it = 0; it < 11; ++it) {
        int i = ptid + it * NPROD;     // 0..703
        int r = i >> 4;                // 0..43
        int g = i & 15;
        int ch = c0 + r - RAD;
        bool valid = ((unsigned)ch < (unsigned)CC);
        const float* gp = xb + (size_t)(valid ? ch : 0) * TT + t0 + g * 4;
        unsigned sa = (unsigned)__cvta_generic_to_shared(sbuf + r * SROW + g * 4);
        cp_async_16(sa, gp, valid ? 16 : 0);
    }
}

extern __shared__ float smem[];

__global__ void __launch_bounds__(NTHR, 4)
snn_ws8(const float* __restrict__ x,
        const float* __restrict__ wp,
        float* __restrict__ out) {
    const int tid = threadIdx.x;
    const bool producer = (tid < NPROD);
    const int ptid = tid;
    const int ctid = tid - NPROD;         // consumer channel within tile (0..31)
    const int c0 = blockIdx.x * TILE_C;
    const int b  = blockIdx.y;

    const float* xb = x + (size_t)b * CC * TT;

    float* IN = smem;                     // NBUF tiles of ROWS x SROW
    float* DR = smem + NBUF * IN_TILE;    // 2 tiles of TILE_C x DROW (drive, then spikes in-place)

    // ---- producer setup: Gaussian taps (R1-exact values) ----
    ull kp[KS];
    int s = 0, g = 0;
    if (producer) {
        s = ptid >> 4;                    // strip (0..3): channels s*8..s*8+7
        g = ptid & 15;                    // float4 t-group (0..15)
        float wv = wp[0];
        float sigma = 0.5f * (1.0f + 10.0f) + fminf(fmaxf(wv, 1.0f), 10.0f);
        float inv2s2 = 0.5f / (sigma * sigma);
        float kw[KS];
        float ksum = 0.0f;
#pragma unroll
        for (int j = 0; j < KS; ++j) {
            float r = (float)(j - RAD);
            kw[j] = expf(-r * r * inv2s2);
            ksum += kw[j];
        }
        float kinv = 1.0f / ksum;
#pragma unroll
        for (int j = 0; j < KS; ++j) kp[j] = pack2(kw[j] * kinv);

        // prologue: tiles 0 and 1 in flight
        load_tile(xb, c0, 0, IN, ptid);
        cp_commit();
        load_tile(xb, c0, TILE_T, IN + IN_TILE, ptid);
        cp_commit();
    }

    float mem = 0.0f;                     // consumer LIF state
    float* outbase = out + (size_t)b * CC * TT + (size_t)c0 * TT;

    for (int i = 0; i < NTILES; ++i) {
        if (producer) {
            if (i + 2 < NTILES)
                load_tile(xb, c0, (i + 2) * TILE_T, IN + ((i + 2) % NBUF) * IN_TILE, ptid);
            cp_commit();
            cp_wait2();                   // tile i's data landed
            bar_prod();

            // ---- strip-8 conv of tile i: rows s*8 .. s*8+19, outputs ch s*8+k ----
            const float* sb = IN + (i % NBUF) * IN_TILE + (s * 8) * SROW + g * 4;
            V2 acc[8], xc[8];
#pragma unroll
            for (int k = 0; k < 8; ++k) { acc[k].u.x = 0ull; acc[k].u.y = 0ull; }
#pragma unroll
            for (int m = 0; m < 20; ++m) {
                V2 v;
                v.u = *(const ulonglong2*)(sb + m * SROW);
#pragma unroll
                for (int k = 0; k < 8; ++k) {
                    int j = m - k;
                    if (j >= 0 && j < KS) {
                        ffma2(acc[k].u.x, v.u.x, kp[j]);
                        ffma2(acc[k].u.y, v.u.y, kp[j]);
                        if (j == RAD) xc[k] = v;
                    }
                }
            }
            float* dst = DR + (i & 1) * DR_TILE + (s * 8) * DROW + g * 4;
#pragma unroll
            for (int k = 0; k < 8; ++k) {
                float4 d4;
                d4.x = xc[k].f.x - acc[k].f.x;
                d4.y = xc[k].f.y - acc[k].f.y;
                d4.z = xc[k].f.z - acc[k].f.z;
                d4.w = xc[k].f.w - acc[k].f.w;
                *(float4*)(dst + k * DROW) = d4;
            }
        }

        __syncthreads();    // publish DR[i&1]; producers reuse it only at i+2

        if (!producer) {
            // ---- LIF scan tile i (bit-identical to R1); spikes written in-place ----
            float* dr = DR + (i & 1) * DR_TILE + ctid * DROW;
#pragma unroll
            for (int gg = 0; gg < TILE_T / 4; ++gg) {
                float4 d4 = *(const float4*)(dr + gg * 4);
                float4 spk;
                mem = fmaf(BETA, mem, d4.x) - ((mem > THRV) ? THRV : 0.0f);
                spk.x = (mem > THRV) ? 1.0f : 0.0f;
                mem = fmaf(BETA, mem, d4.y) - ((mem > THRV) ? THRV : 0.0f);
                spk.y = (mem > THRV) ? 1.0f : 0.0f;
                mem = fmaf(BETA, mem, d4.z) - ((mem > THRV) ? THRV : 0.0f);
                spk.z = (mem > THRV) ? 1.0f : 0.0f;
                mem = fmaf(BETA, mem, d4.w) - ((mem > THRV) ? THRV : 0.0f);
                spk.w = (mem > THRV) ? 1.0f : 0.0f;
                *(float4*)(dr + gg * 4) = spk;
            }
            __syncwarp();   // all lanes' spike rows visible within the warp

            // ---- coalesced writeback: lanes run along t (2 rows x 256B per op) ----
            const float* sp = DR + (i & 1) * DR_TILE;
#pragma unroll
            for (int it = 0; it < 16; ++it) {
                int idx = ctid + it * 32;      // 0..511
                int r  = idx >> 4;             // channel row 0..31
                int gg = idx & 15;             // t-quad 0..15
                float4 v = *(const float4*)(sp + r * DROW + gg * 4);
                *(float4*)(outbase + (size_t)r * TT + (size_t)i * TILE_T + gg * 4) = v;
            }
        }
    }
}

extern "C" void kernel_launch(void* const* d_in, const int* in_sizes, int n_in,
                              void* d_out, int out_size) {
    const float* inp = (const float*)d_in[0];
    const float* wv  = (const float*)d_in[1];
    float* out       = (float*)d_out;

    cudaFuncSetAttribute(snn_ws8, cudaFuncAttributeMaxDynamicSharedMemorySize,
                         SMEM_FLOATS * 4);

    dim3 grid(CC / TILE_C, BB);   // (16, 32) = 512 CTAs
    dim3 blk(NTHR);               // 96 threads: 2 producer + 1 consumer warps
    snn_ws8<<<grid, blk, SMEM_FLOATS * 4>>>(inp, wv, out);
}